// round 10
// baseline (speedup 1.0000x reference)
#include <cuda_runtime.h>
#include <cuda_fp16.h>

#define NT   256     // tags
#define NTH  128     // column pairs
#define BATCH 64
#define SEQ  1024

// E[i][jp] = (exp(T[i][2jp]), exp(T[i][2jp+1])) as half2. 128 KB static.
// T ~ N(0,1): exp(T) <= ~150, inside fp16 range; 32-term partials <= ~4800.
__device__ __align__(16) __half2 g_E[NT * NTH];
__device__ int g_tags64;    // 1 if tags buffer is int64
__device__ int g_mask_i32;  // 1 if mask buffer is int32 (bool promoted), 0 if bytes

// ---------------------------------------------------------------------------
// Prep: E = exp(T) fp16 pairs + dtype sniffs for tags and mask.
//   tags int64  <=> all odd 32-bit words are zero (tags < 256)
//   mask int32  <=> no 32-bit word >= 256 (byte-packed ones give 0x01010101)
// ---------------------------------------------------------------------------
__global__ void crf_prep(const float* __restrict__ trans,
                         const unsigned int* __restrict__ tagsW,
                         const unsigned int* __restrict__ maskW) {
    __shared__ int sTagOdd, sMaskBig;
    int tid = threadIdx.x;                      // 1024 threads
    if (tid == 0) { sTagOdd = 0; sMaskBig = 0; }
    __syncthreads();

    int to = 0, mb = 0;
    for (int k = tid; k < 16384; k += 1024) {
        if ((k & 1) && tagsW[k]) to = 1;        // nonzero odd word -> tags are int32
        if (maskW[k] >= 256u)    mb = 1;        // big word -> mask is byte-packed
    }
    if (to) atomicOr(&sTagOdd, 1);
    if (mb) atomicOr(&sMaskBig, 1);

    for (int p = tid; p < NT * NTH; p += 1024) {
        int i  = p >> 7;
        int jp = p & 127;
        float a = __expf(trans[i * NT + 2 * jp]);
        float b = __expf(trans[i * NT + 2 * jp + 1]);
        g_E[i * NTH + jp] = __floats2half2_rn(a, b);
    }
    __syncthreads();
    if (tid == 0) {
        g_tags64   = sTagOdd  ? 0 : 1;
        g_mask_i32 = sMaskBig ? 0 : 1;
    }
}

// ---------------------------------------------------------------------------
// Forward kernel: one CTA per batch, 256 threads.
// Thread (q = tid>>7, jp = tid&127) owns E rows i in [q*128, q*128+128) for
// column pair (2jp, 2jp+1), held in 128 half2 REGISTERS. Per step:
//   mainloop: acc += p2s[i] * Ereg[k]   (HFMA2, p broadcast from smem)
//   epilogue: S = q0+q1 partials, t = logS + emit, M = max t, r = t-M,
//             p = exp(r), off += M
// ---------------------------------------------------------------------------
__global__ __launch_bounds__(256, 1) void crf_forward(
    const float* __restrict__ inputs,        // [64,1024,256] f32
    const void* __restrict__ tags,           // [64,1024] i32 or i64 (sniffed)
    const void* __restrict__ mask,           // [64,1024] i32 or bytes (sniffed)
    const float* __restrict__ trans,         // [256,256]
    const float* __restrict__ startt,        // [256]
    const float* __restrict__ stopt,         // [256]
    float* __restrict__ out)                 // [64]
{
    __shared__ __align__(16) __half2 p2s[NT];     // p_i duplicated into both halves
    __shared__ float2 parts[2][NTH];              // per-q partial sums
    __shared__ float  wred[8];
    __shared__ float  sscore;

    const int b    = blockIdx.x;
    const int tid  = threadIdx.x;
    const int jp   = tid & 127;
    const int q    = tid >> 7;
    const int lane = tid & 31;
    const int w    = tid >> 5;
    const int j0 = 2 * jp, j1 = 2 * jp + 1;

    const float* emitB = inputs + (size_t)b * SEQ * NT;

    const int mask_i32 = g_mask_i32;
    const int*           maskI = (const int*)mask + (size_t)b * SEQ;
    const unsigned char* maskC = (const unsigned char*)mask + (size_t)b * SEQ;
    #define MASK_AT(t) (mask_i32 ? maskI[t] : (int)maskC[t])

    const int tags64 = g_tags64;
    const int*       tagB32 = (const int*)tags + (size_t)b * SEQ;
    const long long* tagB64 = (const long long*)tags + (size_t)b * SEQ;

    // ---------------- numerator (log score) ----------------
    float sc = 0.f;
    for (int t = tid; t < SEQ; t += 256) {
        int tg = tags64 ? (int)tagB64[t] : tagB32[t];
        float mf = MASK_AT(t) ? 1.f : 0.f;
        float e = emitB[t * NT + tg];
        float c;
        if (t == 0) {
            c = startt[tg] + e * mf;                       // start is unmasked
        } else {
            int tp = tags64 ? (int)tagB64[t - 1] : tagB32[t - 1];
            c = (trans[tp * NT + tg] + e) * mf;
            if (t == SEQ - 1) c += stopt[tg] * mf;
        }
        sc += c;
    }
    #pragma unroll
    for (int o = 16; o; o >>= 1) sc += __shfl_xor_sync(0xffffffffu, sc, o);
    if (lane == 0) wred[w] = sc;
    __syncthreads();
    if (tid == 0) {
        float s = 0.f;
        #pragma unroll
        for (int i = 0; i < 8; i++) s += wred[i];
        sscore = s;
    }
    __syncthreads();                                       // wred reused below

    // ---------------- load E slice into registers ----------------
    __half2 Ereg[128];
    {
        const __half2* gE = g_E + (size_t)q * 128 * NTH + jp;
        #pragma unroll
        for (int k = 0; k < 128; k++) Ereg[k] = gE[k * NTH];   // coalesced per warp
    }

    // ---------------- t = 0 init ----------------
    float r0, r1;
    double off;
    {
        float a0 = startt[j0] + emitB[j0];
        float a1 = startt[j1] + emitB[j1];
        float m = fmaxf(a0, a1);
        #pragma unroll
        for (int o = 16; o; o >>= 1) m = fmaxf(m, __shfl_xor_sync(0xffffffffu, m, o));
        if (lane == 0) wred[w] = m;
        __syncthreads();
        float M = wred[0];
        #pragma unroll
        for (int i = 1; i < 8; i++) M = fmaxf(M, wred[i]);
        r0 = a0 - M;
        r1 = a1 - M;
        off = (double)M;
        if (q == 0) {
            p2s[j0] = __float2half2_rn(__expf(r0));
            p2s[j1] = __float2half2_rn(__expf(r1));
        }
    }
    __syncthreads();

    // emission + mask prefetch (2 steps ahead)
    const float2* emit2 = (const float2*)emitB;
    float2 eA = emit2[1 * NTH + jp];
    float2 eB = emit2[2 * NTH + jp];
    int mkA = MASK_AT(1);
    int mkB = MASK_AT(2);

    const __half2* pp = p2s + q * 128;

    // ---------------- main recursion ----------------
    for (int t = 1; t < SEQ; ++t) {
        __half2 acc0 = __float2half2_rn(0.f);
        __half2 acc1 = acc0, acc2 = acc0, acc3 = acc0;
        #pragma unroll
        for (int kb = 0; kb < 32; kb++) {
            uint4 pv = *reinterpret_cast<const uint4*>(pp + 4 * kb);   // broadcast LDS.128
            __half2 p0, p1, p2, p3;
            p0 = *reinterpret_cast<__half2*>(&pv.x);
            p1 = *reinterpret_cast<__half2*>(&pv.y);
            p2 = *reinterpret_cast<__half2*>(&pv.z);
            p3 = *reinterpret_cast<__half2*>(&pv.w);
            acc0 = __hfma2(p0, Ereg[4 * kb + 0], acc0);
            acc1 = __hfma2(p1, Ereg[4 * kb + 1], acc1);
            acc2 = __hfma2(p2, Ereg[4 * kb + 2], acc2);
            acc3 = __hfma2(p3, Ereg[4 * kb + 3], acc3);
        }
        float2 f0 = __half22float2(acc0);
        float2 f1 = __half22float2(acc1);
        float2 f2 = __half22float2(acc2);
        float2 f3 = __half22float2(acc3);
        float2 myp;
        myp.x = (f0.x + f1.x) + (f2.x + f3.x);
        myp.y = (f0.y + f1.y) + (f2.y + f3.y);
        parts[q][jp] = myp;
        __syncthreads();                                   // barrier 1

        float S0 = parts[0][jp].x + parts[1][jp].x;
        float S1 = parts[0][jp].y + parts[1][jp].y;
        float t0 = __logf(S0) + eA.x;
        float t1 = __logf(S1) + eA.y;
        float m = fmaxf(t0, t1);
        #pragma unroll
        for (int o = 16; o; o >>= 1) m = fmaxf(m, __shfl_xor_sync(0xffffffffu, m, o));
        if (lane == 0) wred[w] = m;
        __syncthreads();                                   // barrier 2

        float M = fmaxf(fmaxf(wred[0], wred[1]), fmaxf(wred[2], wred[3]));
        M = fmaxf(M, fmaxf(fmaxf(wred[4], wred[5]), fmaxf(wred[6], wred[7])));
        if (mkA) {                                         // block-uniform mask
            r0 = t0 - M;
            r1 = t1 - M;
            off += (double)M;
            if (q == 0) {
                p2s[j0] = __float2half2_rn(__expf(r0));
                p2s[j1] = __float2half2_rn(__expf(r1));
            }
        }
        // rotate prefetch buffers
        eA = eB; mkA = mkB;
        int tn = t + 2;
        if (tn < SEQ) {
            eB = emit2[tn * NTH + jp];
            mkB = MASK_AT(tn);
        }
        __syncthreads();                                   // barrier 3 (p2s published)
    }

    // ---------------- final logsumexp(alpha + stop) ----------------
    float v0 = r0 + stopt[j0];
    float v1 = r1 + stopt[j1];
    float m = fmaxf(v0, v1);
    #pragma unroll
    for (int o = 16; o; o >>= 1) m = fmaxf(m, __shfl_xor_sync(0xffffffffu, m, o));
    if (lane == 0) wred[w] = m;
    __syncthreads();
    float M = wred[0];
    #pragma unroll
    for (int i = 1; i < 8; i++) M = fmaxf(M, wred[i]);     // q halves duplicate: max ok
    float s = __expf(v0 - M) + __expf(v1 - M);
    #pragma unroll
    for (int o = 16; o; o >>= 1) s += __shfl_xor_sync(0xffffffffu, s, o);
    __syncthreads();                                       // wred reuse fence
    if (lane == 0) wred[w] = s;
    __syncthreads();
    if (tid == 0) {
        float ssum = (wred[0] + wred[1]) + (wred[2] + wred[3]);   // q=0 warps only (q=1 dup)
        double logZ = off + (double)(M + __logf(ssum));
        out[b] = (float)((double)sscore - logZ);
    }
    #undef MASK_AT
}

// ---------------------------------------------------------------------------
extern "C" void kernel_launch(void* const* d_in, const int* in_sizes, int n_in,
                              void* d_out, int out_size) {
    (void)in_sizes; (void)n_in; (void)out_size;
    const float* inputs = (const float*)d_in[0];
    const void*  tags   = d_in[1];
    const void*  msk    = d_in[2];
    const float* trans  = (const float*)d_in[3];
    const float* startt = (const float*)d_in[4];
    const float* stopt  = (const float*)d_in[5];
    float* out = (float*)d_out;

    crf_prep<<<1, 1024>>>(trans, (const unsigned int*)tags, (const unsigned int*)msk);
    crf_forward<<<BATCH, 256>>>(inputs, tags, msk, trans, startt, stopt, out);
}

// round 12
// speedup vs baseline: 1.1193x; 1.1193x over previous
#include <cuda_runtime.h>
#include <cuda_fp16.h>

#define NT   256     // tags
#define BATCH 64
#define SEQ  1024

// E2t[j*128 + k] = (exp(T[2k][j]), exp(T[2k+1][j])) as half2: column j, row pair k.
// T ~ N(0,1): exp(T) <= ~150, fp16-safe. With exact per-step max, p <= 1, so
// 32-term fp16 partial streams are bounded by ~3500 << 65504 (proven in R10).
__device__ __align__(16) __half2 g_E2t[NT * 128];
__device__ int g_tags64;    // 1 if tags buffer is int64
__device__ int g_mask_i32;  // 1 if mask buffer is int32 (bool promoted)

// ---------------------------------------------------------------------------
// Prep: dtype sniffs + E2t = exp(T) transposed into column-major half2 pairs.
// ---------------------------------------------------------------------------
__global__ void crf_prep(const float* __restrict__ trans,
                         const unsigned int* __restrict__ tagsW,
                         const unsigned int* __restrict__ maskW) {
    __shared__ int sTagOdd, sMaskBig;
    int tid = threadIdx.x;                      // 1024 threads
    if (tid == 0) { sTagOdd = 0; sMaskBig = 0; }
    __syncthreads();

    int to = 0, mb = 0;
    for (int k = tid; k < 16384; k += 1024) {
        if ((k & 1) && tagsW[k]) to = 1;        // nonzero odd word -> tags are int32
        if (maskW[k] >= 256u)    mb = 1;        // big word -> mask is byte-packed
    }
    if (to) atomicOr(&sTagOdd, 1);
    if (mb) atomicOr(&sMaskBig, 1);

    for (int idx = tid; idx < NT * 128; idx += 1024) {
        int j = idx >> 7;                       // column
        int k = idx & 127;                      // row pair
        float a = __expf(trans[(2 * k)     * NT + j]);
        float b = __expf(trans[(2 * k + 1) * NT + j]);
        g_E2t[j * 128 + k] = __floats2half2_rn(a, b);
    }
    __syncthreads();
    if (tid == 0) {
        g_tags64   = sTagOdd  ? 0 : 1;
        g_mask_i32 = sMaskBig ? 0 : 1;
    }
}

// ---------------------------------------------------------------------------
// Forward: one CTA per batch, 256 threads; thread j owns full column j of E
// in 128 half2 registers (row-pair packed). Per step (TWO barriers):
//   S_j = sum_k p2[k] . E2[k]     (128 HFMA2, thread-local full sum)
//   tt  = logf(S_j) + e_t
//   warp max -> wred; BAR_A; M = exact global max (=> r <= 0, fp16 safe)
//   r = tt - M, off += M (if mask); publish p=exp(r) -> pbuf[(t+1)&1]; BAR_B
// ---------------------------------------------------------------------------
__global__ __launch_bounds__(256, 1) void crf_forward(
    const float* __restrict__ inputs,        // [64,1024,256] f32
    const void* __restrict__ tags,           // [64,1024] i32 or i64 (sniffed)
    const void* __restrict__ mask,           // [64,1024] i32 or bytes (sniffed)
    const float* __restrict__ trans,         // [256,256]
    const float* __restrict__ startt,        // [256]
    const float* __restrict__ stopt,         // [256]
    float* __restrict__ out)                 // [64]
{
    __shared__ __align__(16) __half pbuf[2][NT];  // ping-pong p (fp16)
    __shared__ float wred[8];
    __shared__ float sscore;

    const int b    = blockIdx.x;
    const int tid  = threadIdx.x;                 // == column j
    const int lane = tid & 31;
    const int w    = tid >> 5;

    const float* emitB = inputs + (size_t)b * SEQ * NT;

    const int mask_i32 = g_mask_i32;
    const int*           maskI = (const int*)mask + (size_t)b * SEQ;
    const unsigned char* maskC = (const unsigned char*)mask + (size_t)b * SEQ;
    #define MASK_AT(t) (mask_i32 ? maskI[t] : (int)maskC[t])

    const int tags64 = g_tags64;
    const int*       tagB32 = (const int*)tags + (size_t)b * SEQ;
    const long long* tagB64 = (const long long*)tags + (size_t)b * SEQ;

    // ---------------- numerator (log score) ----------------
    float sc = 0.f;
    for (int t = tid; t < SEQ; t += 256) {
        int tg = tags64 ? (int)tagB64[t] : tagB32[t];
        float mf = MASK_AT(t) ? 1.f : 0.f;
        float e = emitB[t * NT + tg];
        float c;
        if (t == 0) {
            c = startt[tg] + e * mf;                       // start is unmasked
        } else {
            int tp = tags64 ? (int)tagB64[t - 1] : tagB32[t - 1];
            c = (trans[tp * NT + tg] + e) * mf;
            if (t == SEQ - 1) c += stopt[tg] * mf;
        }
        sc += c;
    }
    #pragma unroll
    for (int o = 16; o; o >>= 1) sc += __shfl_xor_sync(0xffffffffu, sc, o);
    if (lane == 0) wred[w] = sc;
    __syncthreads();
    if (tid == 0) {
        float s = 0.f;
        #pragma unroll
        for (int i = 0; i < 8; i++) s += wred[i];
        sscore = s;
    }

    // ---------------- load E column j into registers ----------------
    __half2 Ereg[128];
    {
        const uint4* gE = reinterpret_cast<const uint4*>(g_E2t + (size_t)tid * 128);
        #pragma unroll
        for (int k4 = 0; k4 < 32; k4++) {
            uint4 v = gE[k4];
            Ereg[4 * k4 + 0] = *reinterpret_cast<__half2*>(&v.x);
            Ereg[4 * k4 + 1] = *reinterpret_cast<__half2*>(&v.y);
            Ereg[4 * k4 + 2] = *reinterpret_cast<__half2*>(&v.z);
            Ereg[4 * k4 + 3] = *reinterpret_cast<__half2*>(&v.w);
        }
    }
    __syncthreads();                                       // sscore read done; wred free

    // ---------------- t = 0 init (exact max) ----------------
    float r;
    double off;
    {
        float a = startt[tid] + emitB[tid];
        float m = a;
        #pragma unroll
        for (int o = 16; o; o >>= 1) m = fmaxf(m, __shfl_xor_sync(0xffffffffu, m, o));
        if (lane == 0) wred[w] = m;
        __syncthreads();
        float M0 = fmaxf(fmaxf(wred[0], wred[1]), fmaxf(wred[2], wred[3]));
        M0 = fmaxf(M0, fmaxf(fmaxf(wred[4], wred[5]), fmaxf(wred[6], wred[7])));
        r = a - M0;                                        // r <= 0
        off = (double)M0;
        pbuf[1][tid] = __float2half(__expf(r));            // step 1 reads pbuf[1]
    }
    __syncthreads();

    // emission + mask prefetch (2 ahead), scalar per thread
    float eA = emitB[1 * NT + tid];
    float eB = emitB[2 * NT + tid];
    int mkA = MASK_AT(1);
    int mkB = MASK_AT(2);

    // ---------------- main recursion: TWO barriers per step ----------------
    for (int t = 1; t < SEQ; ++t) {
        const int rb = t & 1, wb = (t + 1) & 1;

        const uint4* pp = reinterpret_cast<const uint4*>(pbuf[rb]);
        __half2 acc0 = __float2half2_rn(0.f);
        __half2 acc1 = acc0, acc2 = acc0, acc3 = acc0;
        #pragma unroll
        for (int kb = 0; kb < 32; kb++) {
            uint4 pv = pp[kb];                             // broadcast LDS.128: 8 p values
            acc0 = __hfma2(*reinterpret_cast<__half2*>(&pv.x), Ereg[4 * kb + 0], acc0);
            acc1 = __hfma2(*reinterpret_cast<__half2*>(&pv.y), Ereg[4 * kb + 1], acc1);
            acc2 = __hfma2(*reinterpret_cast<__half2*>(&pv.z), Ereg[4 * kb + 2], acc2);
            acc3 = __hfma2(*reinterpret_cast<__half2*>(&pv.w), Ereg[4 * kb + 3], acc3);
        }
        float2 f0 = __half22float2(acc0);
        float2 f1 = __half22float2(acc1);
        float2 f2 = __half22float2(acc2);
        float2 f3 = __half22float2(acc3);
        float S = ((f0.x + f0.y) + (f1.x + f1.y)) + ((f2.x + f2.y) + (f3.x + f3.y));
        float tt = __logf(S) + eA;

        // exact global max of tt (current step)
        float mw = tt;
        #pragma unroll
        for (int o = 16; o; o >>= 1) mw = fmaxf(mw, __shfl_xor_sync(0xffffffffu, mw, o));
        if (lane == 0) wred[w] = mw;
        __syncthreads();                                   // BAR_A

        float M = fmaxf(fmaxf(wred[0], wred[1]), fmaxf(wred[2], wred[3]));
        M = fmaxf(M, fmaxf(fmaxf(wred[4], wred[5]), fmaxf(wred[6], wred[7])));
        if (mkA) {                                         // block-uniform mask
            r = tt - M;                                    // r <= 0 -> p <= 1, fp16 safe
            off += (double)M;
        }
        pbuf[wb][tid] = __float2half(__expf(r));

        // rotate prefetch
        eA = eB; mkA = mkB;
        int tn = t + 2;
        if (tn < SEQ) {
            eB = emitB[tn * NT + tid];
            mkB = MASK_AT(tn);
        }
        __syncthreads();                                   // BAR_B (p published, wred free)
    }

    // ---------------- final logsumexp(alpha + stop) ----------------
    float v = r + stopt[tid];
    float m = v;
    #pragma unroll
    for (int o = 16; o; o >>= 1) m = fmaxf(m, __shfl_xor_sync(0xffffffffu, m, o));
    if (lane == 0) wred[w] = m;
    __syncthreads();
    float M = wred[0];
    #pragma unroll
    for (int i = 1; i < 8; i++) M = fmaxf(M, wred[i]);
    float s = __expf(v - M);
    #pragma unroll
    for (int o = 16; o; o >>= 1) s += __shfl_xor_sync(0xffffffffu, s, o);
    __syncthreads();                                       // wred reuse fence
    if (lane == 0) wred[w] = s;
    __syncthreads();
    if (tid == 0) {
        float ssum = ((wred[0] + wred[1]) + (wred[2] + wred[3]))
                   + ((wred[4] + wred[5]) + (wred[6] + wred[7]));
        double logZ = off + (double)(M + __logf(ssum));
        out[b] = (float)((double)sscore - logZ);
    }
    #undef MASK_AT
}

// ---------------------------------------------------------------------------
extern "C" void kernel_launch(void* const* d_in, const int* in_sizes, int n_in,
                              void* d_out, int out_size) {
    (void)in_sizes; (void)n_in; (void)out_size;
    const float* inputs = (const float*)d_in[0];
    const void*  tags   = d_in[1];
    const void*  msk    = d_in[2];
    const float* trans  = (const float*)d_in[3];
    const float* startt = (const float*)d_in[4];
    const float* stopt  = (const float*)d_in[5];
    float* out = (float*)d_out;

    crf_prep<<<1, 1024>>>(trans, (const unsigned int*)tags, (const unsigned int*)msk);
    crf_forward<<<BATCH, 256>>>(inputs, tags, msk, trans, startt, stopt, out);
}

// round 15
// speedup vs baseline: 1.2270x; 1.0962x over previous
#include <cuda_runtime.h>
#include <cuda_fp16.h>

#define NT   256     // tags
#define BATCH 64
#define SEQ  1024
#define MU   6.5f    // stationary per-step level growth (measured ~6.55)

// E2t[j*128 + k] = (exp(T[2k][j]), exp(T[2k+1][j])) as half2: column j, row pair k.
// T ~ N(0,1): exp(T) <= ~150, fp16-safe. Predicted shift keeps p~<=5, streams <=~2000.
__device__ __align__(16) __half2 g_E2t[NT * 128];
__device__ int g_tags64;    // 1 if tags buffer is int64
__device__ int g_mask_i32;  // 1 if mask buffer is int32 (bool promoted)

// sm_103 has no redux.sync.f32 — SHFL.BFLY tree (5 x 26 cyc), used off-critical-path.
__device__ __forceinline__ float warp_max_f32(float v) {
    #pragma unroll
    for (int o = 16; o; o >>= 1) v = fmaxf(v, __shfl_xor_sync(0xffffffffu, v, o));
    return v;
}

// ---------------------------------------------------------------------------
// Prep: dtype sniffs + E2t = exp(T) transposed into column-major half2 pairs.
// ---------------------------------------------------------------------------
__global__ void crf_prep(const float* __restrict__ trans,
                         const unsigned int* __restrict__ tagsW,
                         const unsigned int* __restrict__ maskW) {
    __shared__ int sTagOdd, sMaskBig;
    int tid = threadIdx.x;                      // 1024 threads
    if (tid == 0) { sTagOdd = 0; sMaskBig = 0; }
    __syncthreads();

    int to = 0, mb = 0;
    for (int k = tid; k < 16384; k += 1024) {
        if ((k & 1) && tagsW[k]) to = 1;        // nonzero odd word -> tags are int32
        if (maskW[k] >= 256u)    mb = 1;        // big word -> mask is byte-packed
    }
    if (to) atomicOr(&sTagOdd, 1);
    if (mb) atomicOr(&sMaskBig, 1);

    for (int idx = tid; idx < NT * 128; idx += 1024) {
        int j = idx >> 7;                       // column
        int k = idx & 127;                      // row pair
        float a = __expf(trans[(2 * k)     * NT + j]);
        float b = __expf(trans[(2 * k + 1) * NT + j]);
        g_E2t[j * 128 + k] = __floats2half2_rn(a, b);
    }
    __syncthreads();
    if (tid == 0) {
        g_tags64   = sTagOdd  ? 0 : 1;
        g_mask_i32 = sMaskBig ? 0 : 1;
    }
}

// ---------------------------------------------------------------------------
// Forward: one CTA per batch, 256 threads; thread j owns full column j of E
// in 128 half2 registers (row-pair packed). ONE barrier per step:
//   rho = combine(wbuf[rb])   (last step's global max of r; OFF critical path)
//   C   = rho + MU            (predicted shift; exact for ANY C)
//   S_j = sum_k p2[k].E2[k]   (128 HFMA2, thread-local)
//   tt  = logf(S_j) + e_t
//   if mask: r = tt - C, off += C        (else alpha unchanged: exact)
//   publish exp(r) -> pbuf[wb], warp-max(r) -> wbuf[wb];  BAR
// ---------------------------------------------------------------------------
__global__ __launch_bounds__(256, 1) void crf_forward(
    const float* __restrict__ inputs,        // [64,1024,256] f32
    const void* __restrict__ tags,           // [64,1024] i32 or i64 (sniffed)
    const void* __restrict__ mask,           // [64,1024] i32 or bytes (sniffed)
    const float* __restrict__ trans,         // [256,256]
    const float* __restrict__ startt,        // [256]
    const float* __restrict__ stopt,         // [256]
    float* __restrict__ out)                 // [64]
{
    __shared__ __align__(16) __half pbuf[2][NT];  // ping-pong p~ (fp16)
    __shared__ float wbuf[2][8];                  // ping-pong per-warp maxes of r
    __shared__ float wred[8];
    __shared__ float sscore;

    const int b    = blockIdx.x;
    const int tid  = threadIdx.x;                 // == column j
    const int lane = tid & 31;
    const int w    = tid >> 5;

    const float* emitB = inputs + (size_t)b * SEQ * NT;

    const int mask_i32 = g_mask_i32;
    const int*           maskI = (const int*)mask + (size_t)b * SEQ;
    const unsigned char* maskC = (const unsigned char*)mask + (size_t)b * SEQ;
    #define MASK_AT(t) (mask_i32 ? maskI[t] : (int)maskC[t])

    const int tags64 = g_tags64;
    const int*       tagB32 = (const int*)tags + (size_t)b * SEQ;
    const long long* tagB64 = (const long long*)tags + (size_t)b * SEQ;

    // ---------------- numerator (log score) ----------------
    float sc = 0.f;
    for (int t = tid; t < SEQ; t += 256) {
        int tg = tags64 ? (int)tagB64[t] : tagB32[t];
        float mf = MASK_AT(t) ? 1.f : 0.f;
        float e = emitB[t * NT + tg];
        float c;
        if (t == 0) {
            c = startt[tg] + e * mf;                       // start is unmasked
        } else {
            int tp = tags64 ? (int)tagB64[t - 1] : tagB32[t - 1];
            c = (trans[tp * NT + tg] + e) * mf;
            if (t == SEQ - 1) c += stopt[tg] * mf;
        }
        sc += c;
    }
    #pragma unroll
    for (int o = 16; o; o >>= 1) sc += __shfl_xor_sync(0xffffffffu, sc, o);
    if (lane == 0) wred[w] = sc;
    __syncthreads();
    if (tid == 0) {
        float s = 0.f;
        #pragma unroll
        for (int i = 0; i < 8; i++) s += wred[i];
        sscore = s;
    }

    // ---------------- load E column j into registers ----------------
    __half2 Ereg[128];
    {
        const uint4* gE = reinterpret_cast<const uint4*>(g_E2t + (size_t)tid * 128);
        #pragma unroll
        for (int k4 = 0; k4 < 32; k4++) {
            uint4 v = gE[k4];
            Ereg[4 * k4 + 0] = *reinterpret_cast<__half2*>(&v.x);
            Ereg[4 * k4 + 1] = *reinterpret_cast<__half2*>(&v.y);
            Ereg[4 * k4 + 2] = *reinterpret_cast<__half2*>(&v.z);
            Ereg[4 * k4 + 3] = *reinterpret_cast<__half2*>(&v.w);
        }
    }
    __syncthreads();                                       // sscore read done; wred free

    // ---------------- t = 0 init (exact max once) ----------------
    float r;
    double off;
    {
        float a = startt[tid] + emitB[tid];
        float m = warp_max_f32(a);
        if (lane == 0) wred[w] = m;
        __syncthreads();
        float M0 = fmaxf(fmaxf(wred[0], wred[1]), fmaxf(wred[2], wred[3]));
        M0 = fmaxf(M0, fmaxf(fmaxf(wred[4], wred[5]), fmaxf(wred[6], wred[7])));
        r = a - M0;                                        // max r = 0
        off = (double)M0;
        pbuf[1][tid] = __float2half(__expf(r));            // step 1 reads pbuf[1]
        float mw = warp_max_f32(r);
        if (lane == 0) { wbuf[1][w] = mw; wbuf[0][w] = mw; }  // step 1 reads wbuf[1]
    }
    __syncthreads();

    // emission + mask prefetch (2 ahead), scalar per thread
    float eA = emitB[1 * NT + tid];
    float eB = emitB[2 * NT + tid];
    int mkA = MASK_AT(1);
    int mkB = MASK_AT(2);

    // ---------------- main recursion: ONE barrier per step ----------------
    for (int t = 1; t < SEQ; ++t) {
        const int rb = t & 1, wb = rb ^ 1;

        // last step's global max of r (off critical path; overlaps matvec via ILP)
        float rho = fmaxf(fmaxf(wbuf[rb][0], wbuf[rb][1]), fmaxf(wbuf[rb][2], wbuf[rb][3]));
        rho = fmaxf(rho, fmaxf(fmaxf(wbuf[rb][4], wbuf[rb][5]), fmaxf(wbuf[rb][6], wbuf[rb][7])));
        float C = rho + MU;                                // predicted shift (exact for any C)

        const uint4* pp = reinterpret_cast<const uint4*>(pbuf[rb]);
        __half2 acc0 = __float2half2_rn(0.f);
        __half2 acc1 = acc0, acc2 = acc0, acc3 = acc0;
        #pragma unroll
        for (int kb = 0; kb < 32; kb++) {
            uint4 pv = pp[kb];                             // broadcast LDS.128: 8 p values
            acc0 = __hfma2(*reinterpret_cast<__half2*>(&pv.x), Ereg[4 * kb + 0], acc0);
            acc1 = __hfma2(*reinterpret_cast<__half2*>(&pv.y), Ereg[4 * kb + 1], acc1);
            acc2 = __hfma2(*reinterpret_cast<__half2*>(&pv.z), Ereg[4 * kb + 2], acc2);
            acc3 = __hfma2(*reinterpret_cast<__half2*>(&pv.w), Ereg[4 * kb + 3], acc3);
        }
        float2 f0 = __half22float2(acc0);
        float2 f1 = __half22float2(acc1);
        float2 f2 = __half22float2(acc2);
        float2 f3 = __half22float2(acc3);
        float S = ((f0.x + f0.y) + (f1.x + f1.y)) + ((f2.x + f2.y) + (f3.x + f3.y));
        float tt = __logf(S) + eA;

        if (mkA) {                                         // block-uniform mask
            r = tt - C;                                    // bounded: ~0 +- 0.8
            off += (double)C;
        }
        pbuf[wb][tid] = __float2half(__expf(r));           // critical-path store

        // publish live max of r for next step's shift (off critical path)
        float mw = warp_max_f32(r);
        if (lane == 0) wbuf[wb][w] = mw;

        // rotate prefetch
        eA = eB; mkA = mkB;
        int tn = t + 2;
        if (tn < SEQ) {
            eB = emitB[tn * NT + tid];
            mkB = MASK_AT(tn);
        }
        __syncthreads();                                   // the ONE barrier
    }

    // ---------------- final logsumexp(alpha + stop) ----------------
    float v = r + stopt[tid];
    float m = warp_max_f32(v);
    if (lane == 0) wred[w] = m;
    __syncthreads();
    float M = wred[0];
    #pragma unroll
    for (int i = 1; i < 8; i++) M = fmaxf(M, wred[i]);
    float s = __expf(v - M);
    #pragma unroll
    for (int o = 16; o; o >>= 1) s += __shfl_xor_sync(0xffffffffu, s, o);
    __syncthreads();                                       // wred reuse fence
    if (lane == 0) wred[w] = s;
    __syncthreads();
    if (tid == 0) {
        float ssum = ((wred[0] + wred[1]) + (wred[2] + wred[3]))
                   + ((wred[4] + wred[5]) + (wred[6] + wred[7]));
        double logZ = off + (double)(M + __logf(ssum));
        out[b] = (float)((double)sscore - logZ);
    }
    #undef MASK_AT
}

// ---------------------------------------------------------------------------
extern "C" void kernel_launch(void* const* d_in, const int* in_sizes, int n_in,
                              void* d_out, int out_size) {
    (void)in_sizes; (void)n_in; (void)out_size;
    const float* inputs = (const float*)d_in[0];
    const void*  tags   = d_in[1];
    const void*  msk    = d_in[2];
    const float* trans  = (const float*)d_in[3];
    const float* startt = (const float*)d_in[4];
    const float* stopt  = (const float*)d_in[5];
    float* out = (float*)d_out;

    crf_prep<<<1, 1024>>>(trans, (const unsigned int*)tags, (const unsigned int*)msk);
    crf_forward<<<BATCH, 256>>>(inputs, tags, msk, trans, startt, stopt, out);
}

// round 16
// speedup vs baseline: 1.4960x; 1.2192x over previous
#include <cuda_runtime.h>
#include <cuda_fp16.h>

#define NT   256     // tags
#define BATCH 64
#define SEQ  1024
#define KSHIFT 12    // 2^-k normalizer offset: targets max p ~ 0.25

// E2t[j*128 + k] = (exp(T[2k][j]), exp(T[2k+1][j])) as half2: column j, row pair k.
// T ~ N(0,1): exp(T) <= ~150, fp16-safe; normalized p <= ~0.5 -> streams <= ~2000.
__device__ __align__(16) __half2 g_E2t[NT * 128];
__device__ int g_tags64;    // 1 if tags buffer is int64
__device__ int g_mask_i32;  // 1 if mask buffer is int32 (bool promoted)

__device__ __forceinline__ float warp_max_f32(float v) {
    #pragma unroll
    for (int o = 16; o; o >>= 1) v = fmaxf(v, __shfl_xor_sync(0xffffffffu, v, o));
    return v;
}

// ---------------------------------------------------------------------------
// Prep: dtype sniffs + E2t = exp(T) transposed into column-major half2 pairs.
// ---------------------------------------------------------------------------
__global__ void crf_prep(const float* __restrict__ trans,
                         const unsigned int* __restrict__ tagsW,
                         const unsigned int* __restrict__ maskW) {
    __shared__ int sTagOdd, sMaskBig;
    int tid = threadIdx.x;                      // 1024 threads
    if (tid == 0) { sTagOdd = 0; sMaskBig = 0; }
    __syncthreads();

    int to = 0, mb = 0;
    for (int k = tid; k < 16384; k += 1024) {
        if ((k & 1) && tagsW[k]) to = 1;        // nonzero odd word -> tags are int32
        if (maskW[k] >= 256u)    mb = 1;        // big word -> mask is byte-packed
    }
    if (to) atomicOr(&sTagOdd, 1);
    if (mb) atomicOr(&sMaskBig, 1);

    for (int idx = tid; idx < NT * 128; idx += 1024) {
        int j = idx >> 7;                       // column
        int k = idx & 127;                      // row pair
        float a = __expf(trans[(2 * k)     * NT + j]);
        float b = __expf(trans[(2 * k + 1) * NT + j]);
        g_E2t[j * 128 + k] = __floats2half2_rn(a, b);
    }
    __syncthreads();
    if (tid == 0) {
        g_tags64   = sTagOdd  ? 0 : 1;
        g_mask_i32 = sMaskBig ? 0 : 1;
    }
}

// ---------------------------------------------------------------------------
// Forward: one CTA per batch, 256 threads; thread j owns full column j of E
// in 128 half2 registers. LINEAR-DOMAIN recursion, ONE barrier per step,
// no log/exp on the critical path:
//   k    = exponent(ubuf[ir]) + KSHIFT      (1-step-stale max of p; off-path)
//   ws   = __expf(e_t) * 2^-k               (off-path, hidden under matvec)
//   S_j  = sum p2.E2  (128 HFMA2)
//   if mask: p = S*ws, ktot += k            (exact: alpha = log p + ktot*ln2 + off0)
//   STS half(p); atomicMax(ubuf[iw], bits(p))  [fire-and-forget];  BAR
// ---------------------------------------------------------------------------
__global__ __launch_bounds__(256, 1) void crf_forward(
    const float* __restrict__ inputs,        // [64,1024,256] f32
    const void* __restrict__ tags,           // [64,1024] i32 or i64 (sniffed)
    const void* __restrict__ mask,           // [64,1024] i32 or bytes (sniffed)
    const float* __restrict__ trans,         // [256,256]
    const float* __restrict__ startt,        // [256]
    const float* __restrict__ stopt,         // [256]
    float* __restrict__ out)                 // [64]
{
    __shared__ __align__(16) __half pbuf[2][NT];  // ping-pong p (fp16)
    __shared__ int   ubuf[3];                     // 3-slot rotating max-of-p (bits)
    __shared__ float wred[8];
    __shared__ float sscore;

    const int b    = blockIdx.x;
    const int tid  = threadIdx.x;                 // == column j
    const int lane = tid & 31;
    const int w    = tid >> 5;

    const float* emitB = inputs + (size_t)b * SEQ * NT;

    const int mask_i32 = g_mask_i32;
    const int*           maskI = (const int*)mask + (size_t)b * SEQ;
    const unsigned char* maskC = (const unsigned char*)mask + (size_t)b * SEQ;
    #define MASK_AT(t) (mask_i32 ? maskI[t] : (int)maskC[t])

    const int tags64 = g_tags64;
    const int*       tagB32 = (const int*)tags + (size_t)b * SEQ;
    const long long* tagB64 = (const long long*)tags + (size_t)b * SEQ;

    // ---------------- numerator (log score) ----------------
    float sc = 0.f;
    for (int t = tid; t < SEQ; t += 256) {
        int tg = tags64 ? (int)tagB64[t] : tagB32[t];
        float mf = MASK_AT(t) ? 1.f : 0.f;
        float e = emitB[t * NT + tg];
        float c;
        if (t == 0) {
            c = startt[tg] + e * mf;                       // start is unmasked
        } else {
            int tp = tags64 ? (int)tagB64[t - 1] : tagB32[t - 1];
            c = (trans[tp * NT + tg] + e) * mf;
            if (t == SEQ - 1) c += stopt[tg] * mf;
        }
        sc += c;
    }
    #pragma unroll
    for (int o = 16; o; o >>= 1) sc += __shfl_xor_sync(0xffffffffu, sc, o);
    if (lane == 0) wred[w] = sc;
    __syncthreads();
    if (tid == 0) {
        float s = 0.f;
        #pragma unroll
        for (int i = 0; i < 8; i++) s += wred[i];
        sscore = s;
    }

    // ---------------- load E column j into registers ----------------
    __half2 Ereg[128];
    {
        const uint4* gE = reinterpret_cast<const uint4*>(g_E2t + (size_t)tid * 128);
        #pragma unroll
        for (int k4 = 0; k4 < 32; k4++) {
            uint4 v = gE[k4];
            Ereg[4 * k4 + 0] = *reinterpret_cast<__half2*>(&v.x);
            Ereg[4 * k4 + 1] = *reinterpret_cast<__half2*>(&v.y);
            Ereg[4 * k4 + 2] = *reinterpret_cast<__half2*>(&v.z);
            Ereg[4 * k4 + 3] = *reinterpret_cast<__half2*>(&v.w);
        }
    }
    __syncthreads();                                       // sscore read done; wred free

    // ---------------- t = 0 init (exact max once) ----------------
    float pf;                                              // my p (fp32, persistent)
    int   ktot = 0;                                        // sum of applied exponents
    double off0;
    {
        float a = startt[tid] + emitB[tid];
        float m = warp_max_f32(a);
        if (lane == 0) wred[w] = m;
        if (tid == 0) { ubuf[0] = 0; ubuf[1] = 0; ubuf[2] = 0; }
        __syncthreads();
        float M0 = fmaxf(fmaxf(wred[0], wred[1]), fmaxf(wred[2], wred[3]));
        M0 = fmaxf(M0, fmaxf(fmaxf(wred[4], wred[5]), fmaxf(wred[6], wred[7])));
        pf = __expf(a - M0);                               // max p = 1
        off0 = (double)M0;
        pbuf[1][tid] = __float2half(pf);                   // step 1 reads pbuf[1]
        atomicMax(&ubuf[0], __float_as_int(pf));           // step 1 reads ubuf[0]
    }
    __syncthreads();

    // emission + mask prefetch (2 ahead), scalar per thread
    float eA = emitB[1 * NT + tid];
    float eB = emitB[2 * NT + tid];
    int mkA = MASK_AT(1);
    int mkB = MASK_AT(2);

    // slot rotation: write iw, read ir, reset iz; (iw,ir,iz) <- (iz,iw,ir)
    int iw = 1, ir = 0, iz = 2;

    // ---------------- main recursion: ONE barrier per step ----------------
    for (int t = 1; t < SEQ; ++t) {
        const int rb = t & 1, wb = rb ^ 1;

        // off-path: normalizer from 1-step-stale max of p (power of two, exact)
        int ib = ubuf[ir];
        int k  = ((ib >> 23) & 0xff) - 127 + KSHIFT;
        k = max(1, min(k, 30));
        float s  = __int_as_float((127 - k) << 23);        // 2^-k
        float ws = __expf(eA) * s;                         // hidden under matvec

        const uint4* pp = reinterpret_cast<const uint4*>(pbuf[rb]);
        __half2 acc0 = __float2half2_rn(0.f);
        __half2 acc1 = acc0, acc2 = acc0, acc3 = acc0;
        #pragma unroll
        for (int kb = 0; kb < 32; kb++) {
            uint4 pv = pp[kb];                             // broadcast LDS.128: 8 p values
            acc0 = __hfma2(*reinterpret_cast<__half2*>(&pv.x), Ereg[4 * kb + 0], acc0);
            acc1 = __hfma2(*reinterpret_cast<__half2*>(&pv.y), Ereg[4 * kb + 1], acc1);
            acc2 = __hfma2(*reinterpret_cast<__half2*>(&pv.z), Ereg[4 * kb + 2], acc2);
            acc3 = __hfma2(*reinterpret_cast<__half2*>(&pv.w), Ereg[4 * kb + 3], acc3);
        }
        float2 f0 = __half22float2(acc0);
        float2 f1 = __half22float2(acc1);
        float2 f2 = __half22float2(acc2);
        float2 f3 = __half22float2(acc3);
        float S = ((f0.x + f0.y) + (f1.x + f1.y)) + ((f2.x + f2.y) + (f3.x + f3.y));

        if (mkA) {                                         // block-uniform mask
            pf = S * ws;                                   // p' = S*exp(e)*2^-k
            ktot += k;
        }
        pbuf[wb][tid] = __float2half(pf);                  // critical-path store

        atomicMax(&ubuf[iw], __float_as_int(pf));          // fire-and-forget level
        if (tid == 0) ubuf[iz] = 0;                        // reset for step t+1

        // rotate prefetch + slots
        eA = eB; mkA = mkB;
        int tn = t + 2;
        if (tn < SEQ) {
            eB = emitB[tn * NT + tid];
            mkB = MASK_AT(tn);
        }
        int t0 = iw; iw = iz; iz = ir; ir = t0;
        __syncthreads();                                   // the ONE barrier
    }

    // ---------------- final logsumexp(alpha + stop) ----------------
    // alpha_j = logf(pf_j) + ktot*ln2 + off0
    float v = __logf(pf) + stopt[tid];
    float m = warp_max_f32(v);
    if (lane == 0) wred[w] = m;
    __syncthreads();
    float M = wred[0];
    #pragma unroll
    for (int i = 1; i < 8; i++) M = fmaxf(M, wred[i]);
    float s = __expf(v - M);
    #pragma unroll
    for (int o = 16; o; o >>= 1) s += __shfl_xor_sync(0xffffffffu, s, o);
    __syncthreads();                                       // wred reuse fence
    if (lane == 0) wred[w] = s;
    __syncthreads();
    if (tid == 0) {
        float ssum = ((wred[0] + wred[1]) + (wred[2] + wred[3]))
                   + ((wred[4] + wred[5]) + (wred[6] + wred[7]));
        double logZ = off0 + (double)ktot * 0.6931471805599453
                    + (double)(M + __logf(ssum));
        out[b] = (float)((double)sscore - logZ);
    }
    #undef MASK_AT
}

// ---------------------------------------------------------------------------
extern "C" void kernel_launch(void* const* d_in, const int* in_sizes, int n_in,
                              void* d_out, int out_size) {
    (void)in_sizes; (void)n_in; (void)out_size;
    const float* inputs = (const float*)d_in[0];
    const void*  tags   = d_in[1];
    const void*  msk    = d_in[2];
    const float* trans  = (const float*)d_in[3];
    const float* startt = (const float*)d_in[4];
    const float* stopt  = (const float*)d_in[5];
    float* out = (float*)d_out;

    crf_prep<<<1, 1024>>>(trans, (const unsigned int*)tags, (const unsigned int*)msk);
    crf_forward<<<BATCH, 256>>>(inputs, tags, msk, trans, startt, stopt, out);
}